// round 11
// baseline (speedup 1.0000x reference)
#include <cuda_runtime.h>
#include <math.h>

#define NN 8192
#define EE 131072
#define CC 16
#define MID 16
#define KV 16
#define CKV 8
#define CO 8
#define SCALE 0.35355339059327373f   // 1/sqrt((ckv/HEADS)*4) = 1/sqrt(8)
#define NEG_INF __int_as_float(0xff800000u)

// ---------------- scratch (static device globals) ----------------
// o-major P layouts:
__device__ float g_P0[NN * KV * MID];          // [n][o][h]
__device__ float g_P1[NN * KV * MID];          // [n][o][h]
__device__ float g_P2[NN * KV * 3 * MID];      // [n][o][q][h]
__device__ float g_P3[NN * KV * 9 * MID];      // [n][o][f][q][h]
__device__ float g_q0[NN * CKV];               // [n][d]
__device__ float g_q1[NN * CKV * 3];           // [n][d][m]
__device__ float g_vv[EE * CKV * 4];           // [e][c][(v0,v1x,v1y,v1z)]
__device__ float g_z[EE * 4];                  // [e][head]  (scaled)
__device__ float g_oo[NN * CKV * 4];           // [n][c][(o0,o1x,o1y,o1z)]
__device__ float g_x0[NN * CC];
__device__ float g_x1[NN * CC * 3];
// CSR by src and by dst
__device__ int g_deg[NN],  g_cur[NN],  g_rs[NN + 1],  g_eperm[EE];
__device__ int g_degd[NN], g_curd[NN], g_rsd[NN + 1], g_epermd[EE];

// ---------------- CSR build (both directions) ----------------
__global__ void k_csr_zero() {
    int i = blockIdx.x * 256 + threadIdx.x;
    if (i < NN) { g_deg[i] = 0; g_cur[i] = 0; g_degd[i] = 0; g_curd[i] = 0; }
}
__global__ void k_csr_count(const int* __restrict__ esrc, const int* __restrict__ edst) {
    int e = blockIdx.x * 256 + threadIdx.x;
    if (e < EE) { atomicAdd(&g_deg[esrc[e]], 1); atomicAdd(&g_degd[edst[e]], 1); }
}
__global__ void k_csr_scan() {     // 1 block, 1024 threads, 8 elems each; src then dst
    __shared__ int tot[1024];
    int t = threadIdx.x;
    int base = t * 8;
    // --- src ---
    {
        int loc[8]; int s = 0;
#pragma unroll
        for (int i = 0; i < 8; i++) { loc[i] = s; s += g_deg[base + i]; }
        tot[t] = s;
        __syncthreads();
        for (int off = 1; off < 1024; off <<= 1) {
            int v = (t >= off) ? tot[t - off] : 0;
            __syncthreads();
            tot[t] += v;
            __syncthreads();
        }
        int excl = (t == 0) ? 0 : tot[t - 1];
#pragma unroll
        for (int i = 0; i < 8; i++) g_rs[base + i] = excl + loc[i];
        if (t == 0) g_rs[NN] = EE;
    }
    __syncthreads();
    // --- dst ---
    {
        int loc[8]; int s = 0;
#pragma unroll
        for (int i = 0; i < 8; i++) { loc[i] = s; s += g_degd[base + i]; }
        tot[t] = s;
        __syncthreads();
        for (int off = 1; off < 1024; off <<= 1) {
            int v = (t >= off) ? tot[t - off] : 0;
            __syncthreads();
            tot[t] += v;
            __syncthreads();
        }
        int excl = (t == 0) ? 0 : tot[t - 1];
#pragma unroll
        for (int i = 0; i < 8; i++) g_rsd[base + i] = excl + loc[i];
        if (t == 0) g_rsd[NN] = EE;
    }
}
__global__ void k_csr_fill(const int* __restrict__ esrc, const int* __restrict__ edst) {
    int e = blockIdx.x * 256 + threadIdx.x;
    if (e < EE) {
        int s = esrc[e];
        g_eperm[g_rs[s] + atomicAdd(&g_cur[s], 1)] = e;
        int d = edst[e];
        g_epermd[g_rsd[d] + atomicAdd(&g_curd[d], 1)] = e;
    }
}

// ---------------- node precompute: thread owns output row j, W in regs ----------------
// Unified j over [0, 224*KVD):
//  [0,16K): P0  [16K,32K): P1  [32K,80K): P2  [80K,224K): P3   (all o-major)
template<int KVD>
__global__ void k_node_pre3(const float* __restrict__ xin0, const float* __restrict__ xin1,
                            int use_g,
                            const float* __restrict__ wnf1, const float* __restrict__ w11) {
    __shared__ float sx[4][128][16];    // [q (3=scalar x0)][node][i]
    const float* x0 = use_g ? g_x0 : xin0;
    const float* x1 = use_g ? g_x1 : xin1;
    int nb = blockIdx.x * 128;
    int t = threadIdx.x;
    for (int idx = t; idx < 128 * 16; idx += 256) sx[3][idx >> 4][idx & 15] = x0[nb * 16 + idx];
    for (int idx = t; idx < 128 * 48; idx += 256) {
        int nl = idx / 48, r = idx % 48;
        sx[r % 3][nl][r / 3] = x1[nb * 48 + idx];
    }

    const int slice = 16 * KVD * 16;
    int j = blockIdx.y * 256 + t;

    int q;
    const float* wrow;
    int wstride;
    float* gptr;
    int gstride;
    if (j < 32 * KVD) {
        q = 3; wstride = 1; gstride = 16 * KVD;
        if (j < 16 * KVD) {
            int o = j / 16, h = j % 16;
            wrow = wnf1 + (h * KVD + o) * 16;
            gptr = g_P0 + j;
        } else {
            int r = j - 16 * KVD;
            int o = r / 16, h = r % 16;
            wrow = wnf1 + slice + (h * KVD + o) * 16;
            gptr = g_P1 + r;
        }
    } else if (j < 80 * KVD) {
        int r = j - 32 * KVD;
        int o = r / 48, h = r % 16;
        q = (r / 16) % 3;
        wrow = wnf1 + 2 * slice + (h * KVD + o) * 16; wstride = 1;
        gptr = g_P2 + r; gstride = 48 * KVD;
    } else {
        int r = j - 80 * KVD;
        int o = r / 144, f = (r / 48) % 3, h = r % 16;
        q = (r / 16) % 3;
        wrow = w11 + (h * KVD + o) * 48 + f; wstride = 3;
        gptr = g_P3 + r; gstride = 144 * KVD;
    }
    float w[16];
#pragma unroll
    for (int i = 0; i < 16; i++) w[i] = wrow[i * wstride];

    __syncthreads();
    const float* xq = &sx[q][0][0];
#pragma unroll 4
    for (int nl = 0; nl < 128; nl++) {
        const float4* xv = (const float4*)(xq + nl * 16);
        float4 xa = xv[0], xb = xv[1], xc = xv[2], xd = xv[3];
        float a = w[0] * xa.x + w[1] * xa.y + w[2] * xa.z + w[3] * xa.w
                + w[4] * xb.x + w[5] * xb.y + w[6] * xb.z + w[7] * xb.w
                + w[8] * xc.x + w[9] * xc.y + w[10] * xc.z + w[11] * xc.w
                + w[12] * xd.x + w[13] * xd.y + w[14] * xd.z + w[15] * xd.w;
        gptr[(nb + nl) * gstride] = a;
    }
}

// ---------------- q vectors ----------------
__global__ void k_q(const float* __restrict__ xin0, const float* __restrict__ xin1,
                    int use_g, const float* __restrict__ wql) {
    const float* x0 = use_g ? g_x0 : xin0;
    const float* x1 = use_g ? g_x1 : xin1;
    int i = blockIdx.x * 256 + threadIdx.x;   // NN*32
    if (i >= NN * 32) return;
    int n = i >> 5, j = i & 31;
    if (j < 8) {
        float a = 0.f;
#pragma unroll
        for (int c = 0; c < 16; c++) a += x0[n * 16 + c] * wql[c * 8 + j];
        g_q0[n * 8 + j] = a;
    } else {
        int r = j - 8; int d = r / 3, m = r % 3;
        float a = 0.f;
#pragma unroll
        for (int c = 0; c < 16; c++) a += x1[n * 48 + c * 3 + m] * wql[128 + c * 8 + d];
        g_q1[n * 24 + r] = a;
    }
}

__device__ __forceinline__ float dot16v(float4 h0, float4 h1, float4 h2, float4 h3,
                                        const float4* P) {
    float4 a = P[0], b = P[1], c = P[2], d = P[3];
    return h0.x * a.x + h0.y * a.y + h0.z * a.z + h0.w * a.w
         + h1.x * b.x + h1.y * b.y + h1.z * b.z + h1.w * b.w
         + h2.x * c.x + h2.y * c.y + h2.z * c.z + h2.w * c.w
         + h3.x * d.x + h3.y * d.y + h3.z * d.z + h3.w * d.w;
}

// ---------------- edge pass A (src-CSR): block per src node, P in SMEM ----------------
// 256 threads = 16 edges x 16 threads(o) per chunk
__global__ void k_edgeA2(const float* __restrict__ ef, const float* __restrict__ w1l,
                         const float* __restrict__ b00, const float* __restrict__ b01,
                         const float* __restrict__ b10, const float* __restrict__ b11,
                         const int* __restrict__ edst) {
    __shared__ float sP0[16 * 20], sP1[16 * 20], sP2[16 * 52], sP3[16 * 148];
    __shared__ float sw1[1024];
    __shared__ float sH[16][64];
    __shared__ float sef[16][16];
    __shared__ float sB[16][34];
    __shared__ float sq[16][32];
    __shared__ int se[16], sdst[16];
    int n = blockIdx.x;
    int start = g_rs[n], end = g_rs[n + 1];
    if (start == end) return;
    int t = threadIdx.x;
    { int o = t >> 4, h = t & 15; sP0[o * 20 + h] = g_P0[n * 256 + t]; sP1[o * 20 + h] = g_P1[n * 256 + t]; }
    for (int i = t; i < 768; i += 256) { int o = i / 48, r = i % 48; sP2[o * 52 + r] = g_P2[n * 768 + i]; }
    for (int i = t; i < 2304; i += 256) { int o = i / 144, r = i % 144; sP3[o * 148 + r] = g_P3[n * 2304 + i]; }
    for (int i = t; i < 1024; i += 256) sw1[i] = w1l[i];

    int le = t >> 4, o = t & 15;
    const float4* p0v = (const float4*)&sP0[o * 20];
    const float4* p1v = (const float4*)&sP1[o * 20];
    const float4* p2v = (const float4*)&sP2[o * 52];
    const float4* p3v = (const float4*)&sP3[o * 148];

    for (int c = start; c < end; c += 16) {
        int ne = min(16, end - c);
        __syncthreads();
        if (t < 16) {
            int e = (t < ne) ? g_eperm[c + t] : g_eperm[c];
            se[t] = e;
            sdst[t] = edst[e];
        }
        __syncthreads();
        { int lle = t >> 4, f = t & 15; if (lle < ne) sef[lle][f] = ef[se[lle] * 16 + f]; }
        for (int idx = t; idx < 16 * 34; idx += 256) {
            int lle = idx / 34, j = idx % 34;
            if (lle < ne) {
                int e = se[lle];
                float v;
                if (j == 0)      v = b00[e];
                else if (j < 4)  v = b10[e * 3 + j - 1];
                else if (j < 7)  v = b01[e * 3 + j - 4];
                else             v = b11[e * 27 + j - 7];
                sB[lle][j] = v;
            }
        }
        for (int idx = t; idx < 16 * 32; idx += 256) {
            int lle = idx >> 5, j = idx & 31;
            if (lle < ne) {
                int dst = sdst[lle];
                sq[lle][j] = (j < 8) ? g_q0[dst * 8 + j] : g_q1[dst * 24 + (j - 8)];
            }
        }
        __syncthreads();
#pragma unroll
        for (int k = 0; k < 4; k++) {
            int idx = t + k * 256;
            int lle = idx >> 6, ph = idx & 63, p = ph >> 4, h = ph & 15;
            if (lle < ne) {
                float a = 0.f;
#pragma unroll
                for (int f = 0; f < 16; f++) a += sef[lle][f] * sw1[p * 256 + f * 16 + h];
                sH[lle][ph] = fmaxf(a, 0.f);
            }
        }
        __syncthreads();
        // message compute: H in registers (float4), P via vector LDS
        const float4* Hv = (const float4*)sH[le];
        float4 h0a = Hv[0],  h0b = Hv[1],  h0c = Hv[2],  h0d = Hv[3];
        float4 h1a = Hv[4],  h1b = Hv[5],  h1c = Hv[6],  h1d = Hv[7];
        float4 h2a = Hv[8],  h2b = Hv[9],  h2c = Hv[10], h2d = Hv[11];
        float4 h3a = Hv[12], h3b = Hv[13], h3c = Hv[14], h3d = Hv[15];

        float a00 = dot16v(h0a, h0b, h0c, h0d, p0v);
        float a01 = dot16v(h1a, h1b, h1c, h1d, p1v);
        float z2[3];
#pragma unroll
        for (int q = 0; q < 3; q++) z2[q] = dot16v(h2a, h2b, h2c, h2d, p2v + q * 4);
        float Z[9];
#pragma unroll
        for (int fq = 0; fq < 9; fq++) Z[fq] = dot16v(h3a, h3b, h3c, h3d, p3v + fq * 4);

        const float* B = sB[le];
        float kv0 = B[0] * a00;
#pragma unroll
        for (int q = 0; q < 3; q++) kv0 += B[1 + q] * z2[q];
        float kv1[3];
#pragma unroll
        for (int p = 0; p < 3; p++) {
            float acc = B[4 + p] * a01;
#pragma unroll
            for (int q = 0; q < 3; q++)
#pragma unroll
                for (int f = 0; f < 3; f++)
                    acc += B[7 + p * 9 + q * 3 + f] * Z[f * 3 + q];
            kv1[p] = acc;
        }
        float zpart = 0.f;
        if (o < 8) {
            zpart = sq[le][o] * kv0;
#pragma unroll
            for (int p = 0; p < 3; p++) zpart += sq[le][8 + o * 3 + p] * kv1[p];
        }
        float zsum = zpart + __shfl_xor_sync(0xffffffffu, zpart, 1);
        if (le < ne) {
            int e = se[le];
            if (o < 8 && (o & 1) == 0) {
                g_z[e * 4 + (o >> 1)] = zsum * SCALE;
            }
            if (o >= 8) {
                int cc = o - 8;
                ((float4*)g_vv)[e * 8 + cc] = make_float4(kv0, kv1[0], kv1[1], kv1[2]);
            }
        }
    }
}

// ---------------- attention aggregate (dst-CSR): warp per dst node, no atomics ----------------
__global__ void k_attn() {
    int w = (blockIdx.x * 256 + threadIdx.x) >> 5;   // node
    int lane = threadIdx.x & 31;
    int start = g_rsd[w], end = g_rsd[w + 1];
    // phase 1: per-head max
    float4 mx = make_float4(NEG_INF, NEG_INF, NEG_INF, NEG_INF);
    for (int i = start + lane; i < end; i += 32) {
        float4 z = ((const float4*)g_z)[g_epermd[i]];
        mx.x = fmaxf(mx.x, z.x); mx.y = fmaxf(mx.y, z.y);
        mx.z = fmaxf(mx.z, z.z); mx.w = fmaxf(mx.w, z.w);
    }
#pragma unroll
    for (int off = 16; off; off >>= 1) {
        mx.x = fmaxf(mx.x, __shfl_xor_sync(0xffffffffu, mx.x, off));
        mx.y = fmaxf(mx.y, __shfl_xor_sync(0xffffffffu, mx.y, off));
        mx.z = fmaxf(mx.z, __shfl_xor_sync(0xffffffffu, mx.z, off));
        mx.w = fmaxf(mx.w, __shfl_xor_sync(0xffffffffu, mx.w, off));
    }
    // phase 2: per-head sum of exp
    float4 sm = make_float4(0.f, 0.f, 0.f, 0.f);
    for (int i = start + lane; i < end; i += 32) {
        float4 z = ((const float4*)g_z)[g_epermd[i]];
        sm.x += __expf(z.x - mx.x); sm.y += __expf(z.y - mx.y);
        sm.z += __expf(z.z - mx.z); sm.w += __expf(z.w - mx.w);
    }
#pragma unroll
    for (int off = 16; off; off >>= 1) {
        sm.x += __shfl_xor_sync(0xffffffffu, sm.x, off);
        sm.y += __shfl_xor_sync(0xffffffffu, sm.y, off);
        sm.z += __shfl_xor_sync(0xffffffffu, sm.z, off);
        sm.w += __shfl_xor_sync(0xffffffffu, sm.w, off);
    }
    // phase 3: aggregate alpha*v; lane = c*4+comp, head = lane>>3
    int head = lane >> 3;
    float m_h = (head == 0) ? mx.x : (head == 1) ? mx.y : (head == 2) ? mx.z : mx.w;
    float s_h = (head == 0) ? sm.x : (head == 1) ? sm.y : (head == 2) ? sm.z : sm.w;
    float inv = 1.f / (s_h + 1e-9f);
    float acc = 0.f;
    for (int i = start; i < end; i++) {
        int e = g_epermd[i];
        float alpha = __expf(g_z[e * 4 + head] - m_h) * inv;
        acc += alpha * g_vv[e * 32 + lane];
    }
    g_oo[w * 32 + lane] = acc;
}

// ---------------- node pass D: projection + SE3 norm ----------------
__global__ void k_nodeD(const float* __restrict__ xin0, const float* __restrict__ xin1,
                        int use_g,
                        const float* __restrict__ wp, const float* __restrict__ gamma,
                        const float* __restrict__ beta) {
    __shared__ float s0[16][24];
    __shared__ float s1[16][72];
    const float* x0 = use_g ? g_x0 : xin0;
    const float* x1 = use_g ? g_x1 : xin1;
    int n0b = blockIdx.x * 16;
    int t = threadIdx.x;
    for (int idx = t; idx < 16 * 24; idx += 256) {
        int nl = idx / 24, c = idx % 24; int n = n0b + nl;
        s0[nl][c] = (c < 8) ? g_oo[(n * 8 + c) * 4] : x0[n * 16 + (c - 8)];
    }
    for (int idx = t; idx < 16 * 72; idx += 256) {
        int nl = idx / 72, r = idx % 72; int c = r / 3, m = r % 3; int n = n0b + nl;
        s1[nl][r] = (c < 8) ? g_oo[(n * 8 + c) * 4 + 1 + m] : x1[n * 48 + (c - 8) * 3 + m];
    }
    __syncthreads();

    int nl = t / 16, d = t % 16; int n = n0b + nl;
    float y0 = 0.f, y1[3] = {0.f, 0.f, 0.f};
#pragma unroll
    for (int c = 0; c < 24; c++) {
        y0 += s0[nl][c] * wp[c * 16 + d];
        float w = wp[384 + c * 16 + d];
        y1[0] += s1[nl][c * 3 + 0] * w;
        y1[1] += s1[nl][c * 3 + 1] * w;
        y1[2] += s1[nl][c * 3 + 2] * w;
    }
    {
        float nv = sqrtf(y0 * y0 + 1e-12f);
        float r = nv;
#pragma unroll
        for (int mk = 1; mk < 16; mk <<= 1) r += __shfl_xor_sync(0xffffffffu, r, mk);
        float mu = r * (1.f / 16.f);
        float dv = nv - mu;
        float v = dv * dv;
#pragma unroll
        for (int mk = 1; mk < 16; mk <<= 1) v += __shfl_xor_sync(0xffffffffu, v, mk);
        v *= (1.f / 16.f);
        float ln = dv * rsqrtf(v + 1e-5f) * gamma[d] + beta[d];
        float fac = fmaxf(ln, 0.f) / (nv + 1e-3f);
        g_x0[n * 16 + d] = y0 * fac;
    }
    {
        float nv = sqrtf(y1[0] * y1[0] + y1[1] * y1[1] + y1[2] * y1[2] + 1e-12f);
        float r = nv;
#pragma unroll
        for (int mk = 1; mk < 16; mk <<= 1) r += __shfl_xor_sync(0xffffffffu, r, mk);
        float mu = r * (1.f / 16.f);
        float dv = nv - mu;
        float v = dv * dv;
#pragma unroll
        for (int mk = 1; mk < 16; mk <<= 1) v += __shfl_xor_sync(0xffffffffu, v, mk);
        v *= (1.f / 16.f);
        float ln = dv * rsqrtf(v + 1e-5f) * gamma[16 + d] + beta[16 + d];
        float fac = fmaxf(ln, 0.f) / (nv + 1e-3f);
        g_x1[n * 48 + d * 3 + 0] = y1[0] * fac;
        g_x1[n * 48 + d * 3 + 1] = y1[1] * fac;
        g_x1[n * 48 + d * 3 + 2] = y1[2] * fac;
    }
}

// ---------------- final: init output with self term ----------------
__global__ void k_initout(const float* __restrict__ wself, float* __restrict__ out) {
    int i = blockIdx.x * 256 + threadIdx.x;   // N*32
    if (i >= NN * 32) return;
    int n = i >> 5, j = i & 31;
    float a = 0.f;
    if (j < 8) {
#pragma unroll
        for (int c = 0; c < 16; c++) a += g_x0[n * 16 + c] * wself[c * 8 + j];
    } else {
        int r = j - 8; int o = r / 3, m = r % 3;
#pragma unroll
        for (int c = 0; c < 16; c++) a += g_x1[n * 48 + c * 3 + m] * wself[128 + c * 8 + o];
    }
    out[i] = a;
}

// ---------------- final fc pass (src-CSR): 32 edges x 8 threads(o) ----------------
__global__ void k_edge_fc2(const float* __restrict__ ef, const float* __restrict__ w1l,
                           const float* __restrict__ b00, const float* __restrict__ b01,
                           const float* __restrict__ b10, const float* __restrict__ b11,
                           const int* __restrict__ edst, float* __restrict__ out) {
    __shared__ float sP0[8 * 20], sP1[8 * 20], sP2[8 * 52], sP3[8 * 148];
    __shared__ float sw1[1024];
    __shared__ float sH[32][64];
    __shared__ float sef[32][16];
    __shared__ float sB[32][34];
    __shared__ int se[32], sdst[32];
    int n = blockIdx.x;
    int start = g_rs[n], end = g_rs[n + 1];
    if (start == end) return;
    int t = threadIdx.x;
    if (t < 128) {
        int o = t >> 4, h = t & 15;
        sP0[o * 20 + h] = g_P0[n * 128 + t];
        sP1[o * 20 + h] = g_P1[n * 128 + t];
    }
    for (int i = t; i < 384; i += 256) { int o = i / 48, r = i % 48; sP2[o * 52 + r] = g_P2[n * 384 + i]; }
    for (int i = t; i < 1152; i += 256) { int o = i / 144, r = i % 144; sP3[o * 148 + r] = g_P3[n * 1152 + i]; }
    for (int i = t; i < 1024; i += 256) sw1[i] = w1l[i];

    int le = t >> 3, o = t & 7;
    const float4* p0v = (const float4*)&sP0[o * 20];
    const float4* p1v = (const float4*)&sP1[o * 20];
    const float4* p2v = (const float4*)&sP2[o * 52];
    const float4* p3v = (const float4*)&sP3[o * 148];

    for (int c = start; c < end; c += 32) {
        int ne = min(32, end - c);
        __syncthreads();
        if (t < 32) {
            int e = (t < ne) ? g_eperm[c + t] : g_eperm[c];
            se[t] = e;
            sdst[t] = edst[e];
        }
        __syncthreads();
        for (int idx = t; idx < 32 * 16; idx += 256) {
            int lle = idx >> 4, f = idx & 15;
            if (lle < ne) sef[lle][f] = ef[se[lle] * 16 + f];
        }
        for (int idx = t; idx < 32 * 34; idx += 256) {
            int lle = idx / 34, j = idx % 34;
            if (lle < ne) {
                int e = se[lle];
                float v;
                if (j == 0)      v = b00[e];
                else if (j < 4)  v = b10[e * 3 + j - 1];
                else if (j < 7)  v = b01[e * 3 + j - 4];
                else             v = b11[e * 27 + j - 7];
                sB[lle][j] = v;
            }
        }
        __syncthreads();
#pragma unroll
        for (int k = 0; k < 8; k++) {
            int idx = t + k * 256;
            int lle = idx >> 6, ph = idx & 63, p = ph >> 4, h = ph & 15;
            if (lle < ne) {
                float a = 0.f;
#pragma unroll
                for (int f = 0; f < 16; f++) a += sef[lle][f] * sw1[p * 256 + f * 16 + h];
                sH[lle][ph] = fmaxf(a, 0.f);
            }
        }
        __syncthreads();
        if (le < ne) {
            const float4* Hv = (const float4*)sH[le];
            float4 h0a = Hv[0],  h0b = Hv[1],  h0c = Hv[2],  h0d = Hv[3];
            float4 h1a = Hv[4],  h1b = Hv[5],  h1c = Hv[6],  h1d = Hv[7];
            float4 h2a = Hv[8],  h2b = Hv[9],  h2c = Hv[10], h2d = Hv[11];
            float4 h3a = Hv[12], h3b = Hv[13], h3c = Hv[14], h3d = Hv[15];

            float a00 = dot16v(h0a, h0b, h0c, h0d, p0v);
            float a01 = dot16v(h1a, h1b, h1c, h1d, p1v);
            float z2[3];
#pragma unroll
            for (int q = 0; q < 3; q++) z2[q] = dot16v(h2a, h2b, h2c, h2d, p2v + q * 4);
            float Z[9];
#pragma unroll
            for (int fq = 0; fq < 9; fq++) Z[fq] = dot16v(h3a, h3b, h3c, h3d, p3v + fq * 4);

            const float* B = sB[le];
            int dst = sdst[le];
            float m0 = B[0] * a00;
#pragma unroll
            for (int q = 0; q < 3; q++) m0 += B[1 + q] * z2[q];
            atomicAdd(&out[dst * 32 + o], m0);
#pragma unroll
            for (int p = 0; p < 3; p++) {
                float acc = B[4 + p] * a01;
#pragma unroll
                for (int q = 0; q < 3; q++)
#pragma unroll
                    for (int f = 0; f < 3; f++)
                        acc += B[7 + p * 9 + q * 3 + f] * Z[f * 3 + q];
                atomicAdd(&out[dst * 32 + 8 + o * 3 + p], acc);
            }
        }
    }
}

// ---------------- host orchestration ----------------
extern "C" void kernel_launch(void* const* d_in, const int* in_sizes, int n_in,
                              void* d_out, int out_size) {
    const float* x0       = (const float*)d_in[0];
    const float* x1       = (const float*)d_in[1];
    const float* ef       = (const float*)d_in[2];
    const float* b00      = (const float*)d_in[3];
    const float* b01      = (const float*)d_in[4];
    const float* b10      = (const float*)d_in[5];
    const float* b11      = (const float*)d_in[6];
    const float* kv_w1    = (const float*)d_in[7];
    const float* kv_wnf1  = (const float*)d_in[8];
    const float* kv_w11   = (const float*)d_in[9];
    const float* wq       = (const float*)d_in[10];
    const float* wproj    = (const float*)d_in[11];
    const float* gam      = (const float*)d_in[12];
    const float* bet      = (const float*)d_in[13];
    const float* fc_w1    = (const float*)d_in[14];
    const float* fc_wnf1  = (const float*)d_in[15];
    const float* fc_w11   = (const float*)d_in[16];
    const float* fc_wself = (const float*)d_in[17];
    const int*   esrc     = (const int*)d_in[18];
    const int*   edst     = (const int*)d_in[19];
    float* out = (float*)d_out;

    // CSR both directions
    k_csr_zero<<<(NN + 255) / 256, 256>>>();
    k_csr_count<<<EE / 256, 256>>>(esrc, edst);
    k_csr_scan<<<1, 1024>>>();
    k_csr_fill<<<EE / 256, 256>>>(esrc, edst);

    for (int l = 0; l < 2; l++) {
        int use_g = (l != 0);
        k_node_pre3<KV><<<dim3(NN / 128, (224 * KV) / 256), 256>>>(
            x0, x1, use_g,
            kv_wnf1 + l * 3 * MID * KV * CC,
            kv_w11  + l * MID * KV * CC * 3);
        k_q<<<(NN * 32) / 256, 256>>>(x0, x1, use_g, wq + l * 2 * CC * CKV);
        k_edgeA2<<<NN, 256>>>(ef, kv_w1 + l * 4 * 16 * 16, b00, b01, b10, b11, edst);
        k_attn<<<(NN * 32) / 256, 256>>>();
        k_nodeD<<<NN / 16, 256>>>(x0, x1, use_g, wproj + l * 768, gam + l * 32, bet + l * 32);
    }
    // final fc pass
    k_node_pre3<CO><<<dim3(NN / 128, (224 * CO) / 256), 256>>>(nullptr, nullptr, 1, fc_wnf1, fc_w11);
    k_initout<<<(NN * 32) / 256, 256>>>(fc_wself, out);
    k_edge_fc2<<<NN, 256>>>(ef, fc_w1, b00, b01, b10, b11, edst, out);
}

// round 12
// speedup vs baseline: 1.5465x; 1.5465x over previous
#include <cuda_runtime.h>
#include <math.h>

#define NN 8192
#define EE 131072
#define CC 16
#define MID 16
#define KV 16
#define CKV 8
#define CO 8
#define SCALE 0.35355339059327373f   // 1/sqrt((ckv/HEADS)*4) = 1/sqrt(8)
#define NEG_INF __int_as_float(0xff800000u)

// ---------------- scratch (static device globals) ----------------
// h-major P layouts (round-10 proven):
__device__ float g_P0[NN * MID * KV];          // [n][h][o]
__device__ float g_P1[NN * MID * KV];          // [n][h][o]
__device__ float g_P2[NN * MID * 3 * KV];      // [n][h][q][o]
__device__ float g_P3[NN * MID * 9 * KV];      // [n][h][f][q][o]
__device__ float g_q0[NN * CKV];               // [n][d]
__device__ float g_q1[NN * CKV * 3];           // [n][d][m]
__device__ float g_vv[EE * CKV * 4];           // [e][c][(v0,v1x,v1y,v1z)]
__device__ float g_z[EE * 4];                  // [e][head]  (scaled)
__device__ float g_oo[NN * CKV * 4];           // [n][c][(o0,o1x,o1y,o1z)]
__device__ float g_x0[NN * CC];
__device__ float g_x1[NN * CC * 3];
// CSR by src and by dst
__device__ int g_deg[NN],  g_cur[NN],  g_rs[NN + 1],  g_eperm[EE];
__device__ int g_degd[NN], g_curd[NN], g_rsd[NN + 1], g_epermd[EE];

// ---------------- CSR build (both directions) ----------------
__global__ void k_csr_zero() {
    int i = blockIdx.x * 256 + threadIdx.x;
    if (i < NN) { g_deg[i] = 0; g_cur[i] = 0; g_degd[i] = 0; g_curd[i] = 0; }
}
__global__ void k_csr_count(const int* __restrict__ esrc, const int* __restrict__ edst) {
    int e = blockIdx.x * 256 + threadIdx.x;
    if (e < EE) { atomicAdd(&g_deg[esrc[e]], 1); atomicAdd(&g_degd[edst[e]], 1); }
}
__global__ void k_csr_scan() {     // 1 block, 1024 threads, 8 elems each; src then dst
    __shared__ int tot[1024];
    int t = threadIdx.x;
    int base = t * 8;
    {
        int loc[8]; int s = 0;
#pragma unroll
        for (int i = 0; i < 8; i++) { loc[i] = s; s += g_deg[base + i]; }
        tot[t] = s;
        __syncthreads();
        for (int off = 1; off < 1024; off <<= 1) {
            int v = (t >= off) ? tot[t - off] : 0;
            __syncthreads();
            tot[t] += v;
            __syncthreads();
        }
        int excl = (t == 0) ? 0 : tot[t - 1];
#pragma unroll
        for (int i = 0; i < 8; i++) g_rs[base + i] = excl + loc[i];
        if (t == 0) g_rs[NN] = EE;
    }
    __syncthreads();
    {
        int loc[8]; int s = 0;
#pragma unroll
        for (int i = 0; i < 8; i++) { loc[i] = s; s += g_degd[base + i]; }
        tot[t] = s;
        __syncthreads();
        for (int off = 1; off < 1024; off <<= 1) {
            int v = (t >= off) ? tot[t - off] : 0;
            __syncthreads();
            tot[t] += v;
            __syncthreads();
        }
        int excl = (t == 0) ? 0 : tot[t - 1];
#pragma unroll
        for (int i = 0; i < 8; i++) g_rsd[base + i] = excl + loc[i];
        if (t == 0) g_rsd[NN] = EE;
    }
}
__global__ void k_csr_fill(const int* __restrict__ esrc, const int* __restrict__ edst) {
    int e = blockIdx.x * 256 + threadIdx.x;
    if (e < EE) {
        int s = esrc[e];
        g_eperm[g_rs[s] + atomicAdd(&g_cur[s], 1)] = e;
        int d = edst[e];
        g_epermd[g_rsd[d] + atomicAdd(&g_curd[d], 1)] = e;
    }
}

// ---------------- node precompute (round-10): thread owns row j, W in regs ----------------
// Unified j over [0, 224*KVD):
//  [0,16K): P0 (x0)  [16K,32K): P1 (x0)  [32K,80K): P2 (x1,q)  [80K,224K): P3 (x1,q)
template<int KVD>
__global__ void k_node_pre3(const float* __restrict__ xin0, const float* __restrict__ xin1,
                            int use_g,
                            const float* __restrict__ wnf1, const float* __restrict__ w11) {
    __shared__ float sx[4][128][16];    // [q (3=scalar x0)][node][i]
    const float* x0 = use_g ? g_x0 : xin0;
    const float* x1 = use_g ? g_x1 : xin1;
    int nb = blockIdx.x * 128;
    int t = threadIdx.x;
    for (int idx = t; idx < 128 * 16; idx += 256) sx[3][idx >> 4][idx & 15] = x0[nb * 16 + idx];
    for (int idx = t; idx < 128 * 48; idx += 256) {
        int nl = idx / 48, r = idx % 48;
        sx[r % 3][nl][r / 3] = x1[nb * 48 + idx];
    }

    const int slice = 16 * KVD * 16;
    int j = blockIdx.y * 256 + t;

    int q;
    const float* wrow;
    int wstride;
    float* gptr;
    int gstride;
    if (j < 32 * KVD) {
        q = 3; wrow = wnf1 + j * 16; wstride = 1;
        if (j < 16 * KVD) { gptr = g_P0 + j; }
        else              { gptr = g_P1 + (j - 16 * KVD); }
        gstride = 16 * KVD;
    } else if (j < 80 * KVD) {
        int r = j - 32 * KVD;
        int h = r / (3 * KVD);
        int o = r % KVD;
        q = (r / KVD) % 3;
        wrow = wnf1 + 2 * slice + (h * KVD + o) * 16; wstride = 1;
        gptr = g_P2 + r; gstride = 48 * KVD;
    } else {
        int r = j - 80 * KVD;
        int h = r / (9 * KVD);
        int f = (r / (3 * KVD)) % 3;
        int o = r % KVD;
        q = (r / KVD) % 3;
        wrow = w11 + (h * KVD + o) * 16 * 3 + f; wstride = 3;
        gptr = g_P3 + r; gstride = 144 * KVD;
    }
    float w[16];
#pragma unroll
    for (int i = 0; i < 16; i++) w[i] = wrow[i * wstride];

    __syncthreads();
    const float* xq = &sx[q][0][0];
#pragma unroll 4
    for (int nl = 0; nl < 128; nl++) {
        const float4* xv = (const float4*)(xq + nl * 16);
        float4 xa = xv[0], xb = xv[1], xc = xv[2], xd = xv[3];
        float a = w[0] * xa.x + w[1] * xa.y + w[2] * xa.z + w[3] * xa.w
                + w[4] * xb.x + w[5] * xb.y + w[6] * xb.z + w[7] * xb.w
                + w[8] * xc.x + w[9] * xc.y + w[10] * xc.z + w[11] * xc.w
                + w[12] * xd.x + w[13] * xd.y + w[14] * xd.z + w[15] * xd.w;
        gptr[(nb + nl) * gstride] = a;
    }
}

// ---------------- q vectors ----------------
__global__ void k_q(const float* __restrict__ xin0, const float* __restrict__ xin1,
                    int use_g, const float* __restrict__ wql) {
    const float* x0 = use_g ? g_x0 : xin0;
    const float* x1 = use_g ? g_x1 : xin1;
    int i = blockIdx.x * 256 + threadIdx.x;   // NN*32
    if (i >= NN * 32) return;
    int n = i >> 5, j = i & 31;
    if (j < 8) {
        float a = 0.f;
#pragma unroll
        for (int c = 0; c < 16; c++) a += x0[n * 16 + c] * wql[c * 8 + j];
        g_q0[n * 8 + j] = a;
    } else {
        int r = j - 8; int d = r / 3, m = r % 3;
        float a = 0.f;
#pragma unroll
        for (int c = 0; c < 16; c++) a += x1[n * 48 + c * 3 + m] * wql[128 + c * 8 + d];
        g_q1[n * 24 + r] = a;
    }
}

// ---------------- edge pass A (src-CSR): block per src node, P in SMEM (round-10) ----------------
// 256 threads = 16 edges x 16 threads(o) per chunk
__global__ void k_edgeA2(const float* __restrict__ ef, const float* __restrict__ w1l,
                         const float* __restrict__ b00, const float* __restrict__ b01,
                         const float* __restrict__ b10, const float* __restrict__ b11,
                         const int* __restrict__ edst) {
    __shared__ float sP0[256], sP1[256], sP2[768], sP3[2304];
    __shared__ float sw1[1024];
    __shared__ float sH[16][64];
    __shared__ float sef[16][16];
    __shared__ float sB[16][34];
    __shared__ float sq[16][32];
    __shared__ int se[16], sdst[16];
    int n = blockIdx.x;
    int start = g_rs[n], end = g_rs[n + 1];
    if (start == end) return;
    int t = threadIdx.x;
    sP0[t] = g_P0[n * 256 + t];
    sP1[t] = g_P1[n * 256 + t];
    for (int i = t; i < 768; i += 256) sP2[i] = g_P2[n * 768 + i];
    for (int i = t; i < 2304; i += 256) sP3[i] = g_P3[n * 2304 + i];
    for (int i = t; i < 1024; i += 256) sw1[i] = w1l[i];

    for (int c = start; c < end; c += 16) {
        int ne = min(16, end - c);
        __syncthreads();
        if (t < 16) {
            int e = (t < ne) ? g_eperm[c + t] : g_eperm[c];
            se[t] = e;
            sdst[t] = edst[e];
        }
        __syncthreads();
        { int le = t >> 4, f = t & 15; if (le < ne) sef[le][f] = ef[se[le] * 16 + f]; }
        for (int idx = t; idx < 16 * 34; idx += 256) {
            int le = idx / 34, j = idx % 34;
            if (le < ne) {
                int e = se[le];
                float v;
                if (j == 0)      v = b00[e];
                else if (j < 4)  v = b10[e * 3 + j - 1];
                else if (j < 7)  v = b01[e * 3 + j - 4];
                else             v = b11[e * 27 + j - 7];
                sB[le][j] = v;
            }
        }
        for (int idx = t; idx < 16 * 32; idx += 256) {
            int le = idx >> 5, j = idx & 31;
            if (le < ne) {
                int dst = sdst[le];
                sq[le][j] = (j < 8) ? g_q0[dst * 8 + j] : g_q1[dst * 24 + (j - 8)];
            }
        }
        __syncthreads();
#pragma unroll
        for (int k = 0; k < 4; k++) {
            int idx = t + k * 256;
            int le = idx >> 6, ph = idx & 63, p = ph >> 4, h = ph & 15;
            if (le < ne) {
                float a = 0.f;
#pragma unroll
                for (int f = 0; f < 16; f++) a += sef[le][f] * sw1[p * 256 + f * 16 + h];
                sH[le][ph] = fmaxf(a, 0.f);
            }
        }
        __syncthreads();
        // message compute (unguarded reads from smem; stores guarded)
        int le = t >> 4, o = t & 15;
        const float* H = sH[le];
        float a00 = 0.f, a01 = 0.f;
        float z2[3] = {0.f, 0.f, 0.f};
        float Z[9] = {0.f, 0.f, 0.f, 0.f, 0.f, 0.f, 0.f, 0.f, 0.f};
#pragma unroll
        for (int h = 0; h < 16; h++) {
            float h0 = H[h], h1 = H[16 + h], h2 = H[32 + h], h3 = H[48 + h];
            a00 += h0 * sP0[h * 16 + o];
            a01 += h1 * sP1[h * 16 + o];
#pragma unroll
            for (int q = 0; q < 3; q++) z2[q] += h2 * sP2[h * 48 + q * 16 + o];
#pragma unroll
            for (int fq = 0; fq < 9; fq++) Z[fq] += h3 * sP3[h * 144 + fq * 16 + o];
        }
        const float* B = sB[le];
        float kv0 = B[0] * a00;
#pragma unroll
        for (int q = 0; q < 3; q++) kv0 += B[1 + q] * z2[q];
        float kv1[3];
#pragma unroll
        for (int p = 0; p < 3; p++) {
            float acc = B[4 + p] * a01;
#pragma unroll
            for (int q = 0; q < 3; q++)
#pragma unroll
                for (int f = 0; f < 3; f++)
                    acc += B[7 + p * 9 + q * 3 + f] * Z[f * 3 + q];
            kv1[p] = acc;
        }
        float zpart = 0.f;
        if (o < 8) {
            zpart = sq[le][o] * kv0;
#pragma unroll
            for (int p = 0; p < 3; p++) zpart += sq[le][8 + o * 3 + p] * kv1[p];
        }
        float zsum = zpart + __shfl_xor_sync(0xffffffffu, zpart, 1);
        if (le < ne) {
            int e = se[le];
            if (o < 8 && (o & 1) == 0) {
                g_z[e * 4 + (o >> 1)] = zsum * SCALE;    // plain store; softmax in k_attn
            }
            if (o >= 8) {
                int cc = o - 8;
                ((float4*)g_vv)[e * 8 + cc] = make_float4(kv0, kv1[0], kv1[1], kv1[2]);
            }
        }
    }
}

// ---------------- attention aggregate (dst-CSR): warp per dst node, no atomics ----------------
__global__ void k_attn() {
    int w = (blockIdx.x * 256 + threadIdx.x) >> 5;   // node
    int lane = threadIdx.x & 31;
    int start = g_rsd[w], end = g_rsd[w + 1];
    // phase 1: per-head max
    float4 mx = make_float4(NEG_INF, NEG_INF, NEG_INF, NEG_INF);
    for (int i = start + lane; i < end; i += 32) {
        float4 z = ((const float4*)g_z)[g_epermd[i]];
        mx.x = fmaxf(mx.x, z.x); mx.y = fmaxf(mx.y, z.y);
        mx.z = fmaxf(mx.z, z.z); mx.w = fmaxf(mx.w, z.w);
    }
#pragma unroll
    for (int off = 16; off; off >>= 1) {
        mx.x = fmaxf(mx.x, __shfl_xor_sync(0xffffffffu, mx.x, off));
        mx.y = fmaxf(mx.y, __shfl_xor_sync(0xffffffffu, mx.y, off));
        mx.z = fmaxf(mx.z, __shfl_xor_sync(0xffffffffu, mx.z, off));
        mx.w = fmaxf(mx.w, __shfl_xor_sync(0xffffffffu, mx.w, off));
    }
    // phase 2: per-head sum of exp
    float4 sm = make_float4(0.f, 0.f, 0.f, 0.f);
    for (int i = start + lane; i < end; i += 32) {
        float4 z = ((const float4*)g_z)[g_epermd[i]];
        sm.x += __expf(z.x - mx.x); sm.y += __expf(z.y - mx.y);
        sm.z += __expf(z.z - mx.z); sm.w += __expf(z.w - mx.w);
    }
#pragma unroll
    for (int off = 16; off; off >>= 1) {
        sm.x += __shfl_xor_sync(0xffffffffu, sm.x, off);
        sm.y += __shfl_xor_sync(0xffffffffu, sm.y, off);
        sm.z += __shfl_xor_sync(0xffffffffu, sm.z, off);
        sm.w += __shfl_xor_sync(0xffffffffu, sm.w, off);
    }
    // phase 3: aggregate alpha*v; lane = c*4+comp, head = lane>>3
    int head = lane >> 3;
    float m_h = (head == 0) ? mx.x : (head == 1) ? mx.y : (head == 2) ? mx.z : mx.w;
    float s_h = (head == 0) ? sm.x : (head == 1) ? sm.y : (head == 2) ? sm.z : sm.w;
    float inv = 1.f / (s_h + 1e-9f);
    float acc = 0.f;
    for (int i = start; i < end; i++) {
        int e = g_epermd[i];
        float alpha = __expf(g_z[e * 4 + head] - m_h) * inv;
        acc += alpha * g_vv[e * 32 + lane];
    }
    g_oo[w * 32 + lane] = acc;
}

// ---------------- node pass D: projection + SE3 norm ----------------
__global__ void k_nodeD(const float* __restrict__ xin0, const float* __restrict__ xin1,
                        int use_g,
                        const float* __restrict__ wp, const float* __restrict__ gamma,
                        const float* __restrict__ beta) {
    __shared__ float s0[16][24];
    __shared__ float s1[16][72];
    const float* x0 = use_g ? g_x0 : xin0;
    const float* x1 = use_g ? g_x1 : xin1;
    int n0b = blockIdx.x * 16;
    int t = threadIdx.x;
    for (int idx = t; idx < 16 * 24; idx += 256) {
        int nl = idx / 24, c = idx % 24; int n = n0b + nl;
        s0[nl][c] = (c < 8) ? g_oo[(n * 8 + c) * 4] : x0[n * 16 + (c - 8)];
    }
    for (int idx = t; idx < 16 * 72; idx += 256) {
        int nl = idx / 72, r = idx % 72; int c = r / 3, m = r % 3; int n = n0b + nl;
        s1[nl][r] = (c < 8) ? g_oo[(n * 8 + c) * 4 + 1 + m] : x1[n * 48 + (c - 8) * 3 + m];
    }
    __syncthreads();

    int nl = t / 16, d = t % 16; int n = n0b + nl;
    float y0 = 0.f, y1[3] = {0.f, 0.f, 0.f};
#pragma unroll
    for (int c = 0; c < 24; c++) {
        y0 += s0[nl][c] * wp[c * 16 + d];
        float w = wp[384 + c * 16 + d];
        y1[0] += s1[nl][c * 3 + 0] * w;
        y1[1] += s1[nl][c * 3 + 1] * w;
        y1[2] += s1[nl][c * 3 + 2] * w;
    }
    {
        float nv = sqrtf(y0 * y0 + 1e-12f);
        float r = nv;
#pragma unroll
        for (int mk = 1; mk < 16; mk <<= 1) r += __shfl_xor_sync(0xffffffffu, r, mk);
        float mu = r * (1.f / 16.f);
        float dv = nv - mu;
        float v = dv * dv;
#pragma unroll
        for (int mk = 1; mk < 16; mk <<= 1) v += __shfl_xor_sync(0xffffffffu, v, mk);
        v *= (1.f / 16.f);
        float ln = dv * rsqrtf(v + 1e-5f) * gamma[d] + beta[d];
        float fac = fmaxf(ln, 0.f) / (nv + 1e-3f);
        g_x0[n * 16 + d] = y0 * fac;
    }
    {
        float nv = sqrtf(y1[0] * y1[0] + y1[1] * y1[1] + y1[2] * y1[2] + 1e-12f);
        float r = nv;
#pragma unroll
        for (int mk = 1; mk < 16; mk <<= 1) r += __shfl_xor_sync(0xffffffffu, r, mk);
        float mu = r * (1.f / 16.f);
        float dv = nv - mu;
        float v = dv * dv;
#pragma unroll
        for (int mk = 1; mk < 16; mk <<= 1) v += __shfl_xor_sync(0xffffffffu, v, mk);
        v *= (1.f / 16.f);
        float ln = dv * rsqrtf(v + 1e-5f) * gamma[16 + d] + beta[16 + d];
        float fac = fmaxf(ln, 0.f) / (nv + 1e-3f);
        g_x1[n * 48 + d * 3 + 0] = y1[0] * fac;
        g_x1[n * 48 + d * 3 + 1] = y1[1] * fac;
        g_x1[n * 48 + d * 3 + 2] = y1[2] * fac;
    }
}

// ---------------- final: init output with self term ----------------
__global__ void k_initout(const float* __restrict__ wself, float* __restrict__ out) {
    int i = blockIdx.x * 256 + threadIdx.x;   // N*32
    if (i >= NN * 32) return;
    int n = i >> 5, j = i & 31;
    float a = 0.f;
    if (j < 8) {
#pragma unroll
        for (int c = 0; c < 16; c++) a += g_x0[n * 16 + c] * wself[c * 8 + j];
    } else {
        int r = j - 8; int o = r / 3, m = r % 3;
#pragma unroll
        for (int c = 0; c < 16; c++) a += g_x1[n * 48 + c * 3 + m] * wself[128 + c * 8 + o];
    }
    out[i] = a;
}

// ---------------- final fc pass (src-CSR): 32 edges x 8 threads(o) (round-10) ----------------
__global__ void k_edge_fc2(const float* __restrict__ ef, const float* __restrict__ w1l,
                           const float* __restrict__ b00, const float* __restrict__ b01,
                           const float* __restrict__ b10, const float* __restrict__ b11,
                           const int* __restrict__ edst, float* __restrict__ out) {
    __shared__ float sP0[128], sP1[128], sP2[384], sP3[1152];
    __shared__ float sw1[1024];
    __shared__ float sH[32][64];
    __shared__ float sef[32][16];
    __shared__ float sB[32][34];
    __shared__ int se[32], sdst[32];
    int n = blockIdx.x;
    int start = g_rs[n], end = g_rs[n + 1];
    if (start == end) return;
    int t = threadIdx.x;
    if (t < 128) { sP0[t] = g_P0[n * 128 + t]; sP1[t] = g_P1[n * 128 + t]; }
    for (int i = t; i < 384; i += 256) sP2[i] = g_P2[n * 384 + i];
    for (int i = t; i < 1152; i += 256) sP3[i] = g_P3[n * 1152 + i];
    for (int i = t; i < 1024; i += 256) sw1[i] = w1l[i];

    for (int c = start; c < end; c += 32) {
        int ne = min(32, end - c);
        __syncthreads();
        if (t < 32) {
            int e = (t < ne) ? g_eperm[c + t] : g_eperm[c];
            se[t] = e;
            sdst[t] = edst[e];
        }
        __syncthreads();
        for (int idx = t; idx < 32 * 16; idx += 256) {
            int le = idx >> 4, f = idx & 15;
            if (le < ne) sef[le][f] = ef[se[le] * 16 + f];
        }
        for (int idx = t; idx < 32 * 34; idx += 256) {
            int le = idx / 34, j = idx % 34;
            if (le < ne) {
                int e = se[le];
                float v;
                if (j == 0)      v = b00[e];
                else if (j < 4)  v = b10[e * 3 + j - 1];
                else if (j < 7)  v = b01[e * 3 + j - 4];
                else             v = b11[e * 27 + j - 7];
                sB[le][j] = v;
            }
        }
        __syncthreads();
#pragma unroll
        for (int k = 0; k < 8; k++) {
            int idx = t + k * 256;
            int le = idx >> 6, ph = idx & 63, p = ph >> 4, h = ph & 15;
            if (le < ne) {
                float a = 0.f;
#pragma unroll
                for (int f = 0; f < 16; f++) a += sef[le][f] * sw1[p * 256 + f * 16 + h];
                sH[le][ph] = fmaxf(a, 0.f);
            }
        }
        __syncthreads();
        int le = t >> 3, o = t & 7;
        if (le < ne) {
            const float* H = sH[le];
            float a00 = 0.f, a01 = 0.f;
            float z2[3] = {0.f, 0.f, 0.f};
            float Z[9] = {0.f, 0.f, 0.f, 0.f, 0.f, 0.f, 0.f, 0.f, 0.f};
#pragma unroll
            for (int h = 0; h < 16; h++) {
                float h0 = H[h], h1 = H[16 + h], h2 = H[32 + h], h3 = H[48 + h];
                a00 += h0 * sP0[h * 8 + o];
                a01 += h1 * sP1[h * 8 + o];
#pragma unroll
                for (int q = 0; q < 3; q++) z2[q] += h2 * sP2[h * 24 + q * 8 + o];
#pragma unroll
                for (int fq = 0; fq < 9; fq++) Z[fq] += h3 * sP3[h * 72 + fq * 8 + o];
            }
            const float* B = sB[le];
            int dst = sdst[le];
            float m0 = B[0] * a00;
#pragma unroll
            for (int q = 0; q < 3; q++) m0 += B[1 + q] * z2[q];
            atomicAdd(&out[dst * 32 + o], m0);
#pragma unroll
            for (int p = 0; p < 3; p++) {
                float acc = B[4 + p] * a01;
#pragma unroll
                for (int q = 0; q < 3; q++)
#pragma unroll
                    for (int f = 0; f < 3; f++)
                        acc += B[7 + p * 9 + q * 3 + f] * Z[f * 3 + q];
                atomicAdd(&out[dst * 32 + 8 + o * 3 + p], acc);
            }
        }
    }
}

// ---------------- host orchestration ----------------
extern "C" void kernel_launch(void* const* d_in, const int* in_sizes, int n_in,
                              void* d_out, int out_size) {
    const float* x0       = (const float*)d_in[0];
    const float* x1       = (const float*)d_in[1];
    const float* ef       = (const float*)d_in[2];
    const float* b00      = (const float*)d_in[3];
    const float* b01      = (const float*)d_in[4];
    const float* b10      = (const float*)d_in[5];
    const float* b11      = (const float*)d_in[6];
    const float* kv_w1    = (const float*)d_in[7];
    const float* kv_wnf1  = (const float*)d_in[8];
    const float* kv_w11   = (const float*)d_in[9];
    const float* wq       = (const float*)d_in[10];
    const float* wproj    = (const float*)d_in[11];
    const float* gam      = (const float*)d_in[12];
    const float* bet      = (const float*)d_in[13];
    const float* fc_w1    = (const float*)d_in[14];
    const float* fc_wnf1  = (const float*)d_in[15];
    const float* fc_w11   = (const float*)d_in[16];
    const float* fc_wself = (const float*)d_in[17];
    const int*   esrc     = (const int*)d_in[18];
    const int*   edst     = (const int*)d_in[19];
    float* out = (float*)d_out;

    // CSR both directions
    k_csr_zero<<<(NN + 255) / 256, 256>>>();
    k_csr_count<<<EE / 256, 256>>>(esrc, edst);
    k_csr_scan<<<1, 1024>>>();
    k_csr_fill<<<EE / 256, 256>>>(esrc, edst);

    for (int l = 0; l < 2; l++) {
        int use_g = (l != 0);
        k_node_pre3<KV><<<dim3(NN / 128, (224 * KV) / 256), 256>>>(
            x0, x1, use_g,
            kv_wnf1 + l * 3 * MID * KV * CC,
            kv_w11  + l * MID * KV * CC * 3);
        k_q<<<(NN * 32) / 256, 256>>>(x0, x1, use_g, wq + l * 2 * CC * CKV);
        k_edgeA2<<<NN, 256>>>(ef, kv_w1 + l * 4 * 16 * 16, b00, b01, b10, b11, edst);
        k_attn<<<(NN * 32) / 256, 256>>>();
        k_nodeD<<<NN / 16, 256>>>(x0, x1, use_g, wproj + l * 768, gam + l * 32, bet + l * 32);
    }
    // final fc pass
    k_node_pre3<CO><<<dim3(NN / 128, (224 * CO) / 256), 256>>>(nullptr, nullptr, 1, fc_wnf1, fc_w11);
    k_initout<<<(NN * 32) / 256, 256>>>(fc_wself, out);
    k_edge_fc2<<<NN, 256>>>(ef, fc_w1, b00, b01, b10, b11, edst, out);
}

// round 13
// speedup vs baseline: 1.6130x; 1.0430x over previous
#include <cuda_runtime.h>
#include <math.h>

#define NN 8192
#define EE 131072
#define CC 16
#define MID 16
#define KV 16
#define CKV 8
#define CO 8
#define SCALE 0.35355339059327373f   // 1/sqrt((ckv/HEADS)*4) = 1/sqrt(8)
#define NEG_INF __int_as_float(0xff800000u)

// ---------------- scratch (static device globals) ----------------
// h-major P layouts:
__device__ float g_P0[NN * MID * KV];          // [n][h][o]
__device__ float g_P1[NN * MID * KV];          // [n][h][o]
__device__ float g_P2[NN * MID * 3 * KV];      // [n][h][q][o]
__device__ float g_P3[NN * MID * 9 * KV];      // [n][h][f][q][o]
__device__ float g_H[EE * 64];                 // [e][p*16+h]  relu(ef @ w1)
__device__ float g_q0[NN * CKV];               // [n][d]
__device__ float g_q1[NN * CKV * 3];           // [n][d][m]
__device__ float g_vv[EE * CKV * 4];           // [e][c][(v0,v1x,v1y,v1z)]
__device__ float g_z[EE * 4];                  // [e][head]  (scaled)
__device__ float g_oo[NN * CKV * 4];           // [n][c][(o0,o1x,o1y,o1z)]
__device__ float g_x0[NN * CC];
__device__ float g_x1[NN * CC * 3];
// CSR by src and by dst
__device__ int g_deg[NN],  g_cur[NN],  g_rs[NN + 1],  g_eperm[EE];
__device__ int g_degd[NN], g_curd[NN], g_rsd[NN + 1], g_epermd[EE];

// ---------------- CSR build (both directions) ----------------
__global__ void k_csr_zero() {
    int i = blockIdx.x * 256 + threadIdx.x;
    if (i < NN) { g_deg[i] = 0; g_cur[i] = 0; g_degd[i] = 0; g_curd[i] = 0; }
}
__global__ void k_csr_count(const int* __restrict__ esrc, const int* __restrict__ edst) {
    int e = blockIdx.x * 256 + threadIdx.x;
    if (e < EE) { atomicAdd(&g_deg[esrc[e]], 1); atomicAdd(&g_degd[edst[e]], 1); }
}
__global__ void k_csr_scan() {     // 1 block, 1024 threads, 8 elems each; src then dst
    __shared__ int tot[1024];
    int t = threadIdx.x;
    int base = t * 8;
    {
        int loc[8]; int s = 0;
#pragma unroll
        for (int i = 0; i < 8; i++) { loc[i] = s; s += g_deg[base + i]; }
        tot[t] = s;
        __syncthreads();
        for (int off = 1; off < 1024; off <<= 1) {
            int v = (t >= off) ? tot[t - off] : 0;
            __syncthreads();
            tot[t] += v;
            __syncthreads();
        }
        int excl = (t == 0) ? 0 : tot[t - 1];
#pragma unroll
        for (int i = 0; i < 8; i++) g_rs[base + i] = excl + loc[i];
        if (t == 0) g_rs[NN] = EE;
    }
    __syncthreads();
    {
        int loc[8]; int s = 0;
#pragma unroll
        for (int i = 0; i < 8; i++) { loc[i] = s; s += g_degd[base + i]; }
        tot[t] = s;
        __syncthreads();
        for (int off = 1; off < 1024; off <<= 1) {
            int v = (t >= off) ? tot[t - off] : 0;
            __syncthreads();
            tot[t] += v;
            __syncthreads();
        }
        int excl = (t == 0) ? 0 : tot[t - 1];
#pragma unroll
        for (int i = 0; i < 8; i++) g_rsd[base + i] = excl + loc[i];
        if (t == 0) g_rsd[NN] = EE;
    }
}
__global__ void k_csr_fill(const int* __restrict__ esrc, const int* __restrict__ edst) {
    int e = blockIdx.x * 256 + threadIdx.x;
    if (e < EE) {
        int s = esrc[e];
        g_eperm[g_rs[s] + atomicAdd(&g_cur[s], 1)] = e;
        int d = edst[e];
        g_epermd[g_rsd[d] + atomicAdd(&g_curd[d], 1)] = e;
    }
}

// ---------------- H precompute: H[e][p*16+h] = relu(sum_f ef[e][f]*w1[p][f][h]) ----------------
// block: 128 edges; 256 threads = 4 edge-subblocks x 64 outputs
__global__ void k_H(const float* __restrict__ ef, const float* __restrict__ w1l) {
    __shared__ float sef[128][16];
    int eb = blockIdx.x * 128;
    int t = threadIdx.x;
    for (int idx = t; idx < 128 * 16; idx += 256) sef[idx >> 4][idx & 15] = ef[eb * 16 + idx];
    int j = t & 63;           // p*16+h
    int sub = t >> 6;         // 0..3
    float w[16];
#pragma unroll
    for (int f = 0; f < 16; f++) w[f] = w1l[(j >> 4) * 256 + f * 16 + (j & 15)];
    __syncthreads();
#pragma unroll 4
    for (int i = 0; i < 32; i++) {
        int le = sub * 32 + i;
        const float4* xv = (const float4*)sef[le];
        float4 xa = xv[0], xb = xv[1], xc = xv[2], xd = xv[3];
        float a = w[0] * xa.x + w[1] * xa.y + w[2] * xa.z + w[3] * xa.w
                + w[4] * xb.x + w[5] * xb.y + w[6] * xb.z + w[7] * xb.w
                + w[8] * xc.x + w[9] * xc.y + w[10] * xc.z + w[11] * xc.w
                + w[12] * xd.x + w[13] * xd.y + w[14] * xd.z + w[15] * xd.w;
        g_H[(eb + le) * 64 + j] = fmaxf(a, 0.f);
    }
}

// ---------------- node precompute: thread owns row j, W in regs ----------------
template<int KVD>
__global__ void k_node_pre3(const float* __restrict__ xin0, const float* __restrict__ xin1,
                            int use_g,
                            const float* __restrict__ wnf1, const float* __restrict__ w11) {
    __shared__ float sx[4][128][16];    // [q (3=scalar x0)][node][i]
    const float* x0 = use_g ? g_x0 : xin0;
    const float* x1 = use_g ? g_x1 : xin1;
    int nb = blockIdx.x * 128;
    int t = threadIdx.x;
    for (int idx = t; idx < 128 * 16; idx += 256) sx[3][idx >> 4][idx & 15] = x0[nb * 16 + idx];
    for (int idx = t; idx < 128 * 48; idx += 256) {
        int nl = idx / 48, r = idx % 48;
        sx[r % 3][nl][r / 3] = x1[nb * 48 + idx];
    }

    const int slice = 16 * KVD * 16;
    int j = blockIdx.y * 256 + t;

    int q;
    const float* wrow;
    int wstride;
    float* gptr;
    int gstride;
    if (j < 32 * KVD) {
        q = 3; wrow = wnf1 + j * 16; wstride = 1;
        if (j < 16 * KVD) { gptr = g_P0 + j; }
        else              { gptr = g_P1 + (j - 16 * KVD); }
        gstride = 16 * KVD;
    } else if (j < 80 * KVD) {
        int r = j - 32 * KVD;
        int h = r / (3 * KVD);
        int o = r % KVD;
        q = (r / KVD) % 3;
        wrow = wnf1 + 2 * slice + (h * KVD + o) * 16; wstride = 1;
        gptr = g_P2 + r; gstride = 48 * KVD;
    } else {
        int r = j - 80 * KVD;
        int h = r / (9 * KVD);
        int f = (r / (3 * KVD)) % 3;
        int o = r % KVD;
        q = (r / KVD) % 3;
        wrow = w11 + (h * KVD + o) * 16 * 3 + f; wstride = 3;
        gptr = g_P3 + r; gstride = 144 * KVD;
    }
    float w[16];
#pragma unroll
    for (int i = 0; i < 16; i++) w[i] = wrow[i * wstride];

    __syncthreads();
    const float* xq = &sx[q][0][0];
#pragma unroll 4
    for (int nl = 0; nl < 128; nl++) {
        const float4* xv = (const float4*)(xq + nl * 16);
        float4 xa = xv[0], xb = xv[1], xc = xv[2], xd = xv[3];
        float a = w[0] * xa.x + w[1] * xa.y + w[2] * xa.z + w[3] * xa.w
                + w[4] * xb.x + w[5] * xb.y + w[6] * xb.z + w[7] * xb.w
                + w[8] * xc.x + w[9] * xc.y + w[10] * xc.z + w[11] * xc.w
                + w[12] * xd.x + w[13] * xd.y + w[14] * xd.z + w[15] * xd.w;
        gptr[(nb + nl) * gstride] = a;
    }
}

// ---------------- q vectors ----------------
__global__ void k_q(const float* __restrict__ xin0, const float* __restrict__ xin1,
                    int use_g, const float* __restrict__ wql) {
    const float* x0 = use_g ? g_x0 : xin0;
    const float* x1 = use_g ? g_x1 : xin1;
    int i = blockIdx.x * 256 + threadIdx.x;   // NN*32
    if (i >= NN * 32) return;
    int n = i >> 5, j = i & 31;
    if (j < 8) {
        float a = 0.f;
#pragma unroll
        for (int c = 0; c < 16; c++) a += x0[n * 16 + c] * wql[c * 8 + j];
        g_q0[n * 8 + j] = a;
    } else {
        int r = j - 8; int d = r / 3, m = r % 3;
        float a = 0.f;
#pragma unroll
        for (int c = 0; c < 16; c++) a += x1[n * 48 + c * 3 + m] * wql[128 + c * 8 + d];
        g_q1[n * 24 + r] = a;
    }
}

// ---------------- edge pass A (src-CSR): block per src node, P in SMEM ----------------
// 256 threads = 16 edges x 16 threads(o) per chunk; H precomputed in g_H
__global__ void k_edgeA2(const float* __restrict__ b00, const float* __restrict__ b01,
                         const float* __restrict__ b10, const float* __restrict__ b11,
                         const int* __restrict__ edst) {
    __shared__ float sP0[256], sP1[256], sP2[768], sP3[2304];
    __shared__ float sH[16][68];        // padded rows: stride 68 kills row-bank aliasing
    __shared__ float sB[16][34];
    __shared__ float sq[16][32];
    __shared__ int se[16], sdst[16];
    int n = blockIdx.x;
    int start = g_rs[n], end = g_rs[n + 1];
    if (start == end) return;
    int t = threadIdx.x;
    sP0[t] = g_P0[n * 256 + t];
    sP1[t] = g_P1[n * 256 + t];
    for (int i = t; i < 768; i += 256) sP2[i] = g_P2[n * 768 + i];
    for (int i = t; i < 2304; i += 256) sP3[i] = g_P3[n * 2304 + i];

    int le = t >> 4, o = t & 15;

    for (int c = start; c < end; c += 16) {
        int ne = min(16, end - c);
        __syncthreads();
        if (t < 16) {
            int e = (t < ne) ? g_eperm[c + t] : g_eperm[c];
            se[t] = e;
            sdst[t] = edst[e];
        }
        __syncthreads();
        // stage H (coalesced from g_H)
        for (int idx = t; idx < 16 * 64; idx += 256) {
            int lle = idx >> 6, j = idx & 63;
            sH[lle][j] = g_H[se[lle] * 64 + j];
        }
        for (int idx = t; idx < 16 * 34; idx += 256) {
            int lle = idx / 34, j = idx % 34;
            if (lle < ne) {
                int e = se[lle];
                float v;
                if (j == 0)      v = b00[e];
                else if (j < 4)  v = b10[e * 3 + j - 1];
                else if (j < 7)  v = b01[e * 3 + j - 4];
                else             v = b11[e * 27 + j - 7];
                sB[lle][j] = v;
            }
        }
        for (int idx = t; idx < 16 * 32; idx += 256) {
            int lle = idx >> 5, j = idx & 31;
            if (lle < ne) {
                int dst = sdst[lle];
                sq[lle][j] = (j < 8) ? g_q0[dst * 8 + j] : g_q1[dst * 24 + (j - 8)];
            }
        }
        __syncthreads();
        // message compute: H read as float4 tiles, P scalar broadcast
        float a00 = 0.f, a01 = 0.f;
        float z2[3] = {0.f, 0.f, 0.f};
        float Z[9] = {0.f, 0.f, 0.f, 0.f, 0.f, 0.f, 0.f, 0.f, 0.f};
#pragma unroll
        for (int ht = 0; ht < 4; ht++) {
            const int hb = ht * 4;
            float4 H0 = *(const float4*)&sH[le][0 + hb];
            float4 H1 = *(const float4*)&sH[le][16 + hb];
            float4 H2 = *(const float4*)&sH[le][32 + hb];
            float4 H3 = *(const float4*)&sH[le][48 + hb];
            float h0v[4] = {H0.x, H0.y, H0.z, H0.w};
            float h1v[4] = {H1.x, H1.y, H1.z, H1.w};
            float h2v[4] = {H2.x, H2.y, H2.z, H2.w};
            float h3v[4] = {H3.x, H3.y, H3.z, H3.w};
#pragma unroll
            for (int k = 0; k < 4; k++) {
                int h = hb + k;
                a00 += h0v[k] * sP0[h * 16 + o];
                a01 += h1v[k] * sP1[h * 16 + o];
                float h2 = h2v[k];
#pragma unroll
                for (int q = 0; q < 3; q++) z2[q] += h2 * sP2[h * 48 + q * 16 + o];
                float h3 = h3v[k];
#pragma unroll
                for (int fq = 0; fq < 9; fq++) Z[fq] += h3 * sP3[h * 144 + fq * 16 + o];
            }
        }
        const float* B = sB[le];
        float kv0 = B[0] * a00;
#pragma unroll
        for (int q = 0; q < 3; q++) kv0 += B[1 + q] * z2[q];
        float kv1[3];
#pragma unroll
        for (int p = 0; p < 3; p++) {
            float acc = B[4 + p] * a01;
#pragma unroll
            for (int q = 0; q < 3; q++)
#pragma unroll
                for (int f = 0; f < 3; f++)
                    acc += B[7 + p * 9 + q * 3 + f] * Z[f * 3 + q];
            kv1[p] = acc;
        }
        float zpart = 0.f;
        if (o < 8) {
            zpart = sq[le][o] * kv0;
#pragma unroll
            for (int p = 0; p < 3; p++) zpart += sq[le][8 + o * 3 + p] * kv1[p];
        }
        float zsum = zpart + __shfl_xor_sync(0xffffffffu, zpart, 1);
        if (le < ne) {
            int e = se[le];
            if (o < 8 && (o & 1) == 0) {
                g_z[e * 4 + (o >> 1)] = zsum * SCALE;
            }
            if (o >= 8) {
                int cc = o - 8;
                ((float4*)g_vv)[e * 8 + cc] = make_float4(kv0, kv1[0], kv1[1], kv1[2]);
            }
        }
    }
}

// ---------------- attention aggregate (dst-CSR): warp per dst node, no atomics ----------------
__global__ void k_attn() {
    int w = (blockIdx.x * 256 + threadIdx.x) >> 5;   // node
    int lane = threadIdx.x & 31;
    int start = g_rsd[w], end = g_rsd[w + 1];
    float4 mx = make_float4(NEG_INF, NEG_INF, NEG_INF, NEG_INF);
    for (int i = start + lane; i < end; i += 32) {
        float4 z = ((const float4*)g_z)[g_epermd[i]];
        mx.x = fmaxf(mx.x, z.x); mx.y = fmaxf(mx.y, z.y);
        mx.z = fmaxf(mx.z, z.z); mx.w = fmaxf(mx.w, z.w);
    }
#pragma unroll
    for (int off = 16; off; off >>= 1) {
        mx.x = fmaxf(mx.x, __shfl_xor_sync(0xffffffffu, mx.x, off));
        mx.y = fmaxf(mx.y, __shfl_xor_sync(0xffffffffu, mx.y, off));
        mx.z = fmaxf(mx.z, __shfl_xor_sync(0xffffffffu, mx.z, off));
        mx.w = fmaxf(mx.w, __shfl_xor_sync(0xffffffffu, mx.w, off));
    }
    float4 sm = make_float4(0.f, 0.f, 0.f, 0.f);
    for (int i = start + lane; i < end; i += 32) {
        float4 z = ((const float4*)g_z)[g_epermd[i]];
        sm.x += __expf(z.x - mx.x); sm.y += __expf(z.y - mx.y);
        sm.z += __expf(z.z - mx.z); sm.w += __expf(z.w - mx.w);
    }
#pragma unroll
    for (int off = 16; off; off >>= 1) {
        sm.x += __shfl_xor_sync(0xffffffffu, sm.x, off);
        sm.y += __shfl_xor_sync(0xffffffffu, sm.y, off);
        sm.z += __shfl_xor_sync(0xffffffffu, sm.z, off);
        sm.w += __shfl_xor_sync(0xffffffffu, sm.w, off);
    }
    int head = lane >> 3;
    float m_h = (head == 0) ? mx.x : (head == 1) ? mx.y : (head == 2) ? mx.z : mx.w;
    float s_h = (head == 0) ? sm.x : (head == 1) ? sm.y : (head == 2) ? sm.z : sm.w;
    float inv = 1.f / (s_h + 1e-9f);
    float acc = 0.f;
    for (int i = start; i < end; i++) {
        int e = g_epermd[i];
        float alpha = __expf(g_z[e * 4 + head] - m_h) * inv;
        acc += alpha * g_vv[e * 32 + lane];
    }
    g_oo[w * 32 + lane] = acc;
}

// ---------------- node pass D: projection + SE3 norm ----------------
__global__ void k_nodeD(const float* __restrict__ xin0, const float* __restrict__ xin1,
                        int use_g,
                        const float* __restrict__ wp, const float* __restrict__ gamma,
                        const float* __restrict__ beta) {
    __shared__ float s0[16][24];
    __shared__ float s1[16][72];
    const float* x0 = use_g ? g_x0 : xin0;
    const float* x1 = use_g ? g_x1 : xin1;
    int n0b = blockIdx.x * 16;
    int t = threadIdx.x;
    for (int idx = t; idx < 16 * 24; idx += 256) {
        int nl = idx / 24, c = idx % 24; int n = n0b + nl;
        s0[nl][c] = (c < 8) ? g_oo[(n * 8 + c) * 4] : x0[n * 16 + (c - 8)];
    }
    for (int idx = t; idx < 16 * 72; idx += 256) {
        int nl = idx / 72, r = idx % 72; int c = r / 3, m = r % 3; int n = n0b + nl;
        s1[nl][r] = (c < 8) ? g_oo[(n * 8 + c) * 4 + 1 + m] : x1[n * 48 + (c - 8) * 3 + m];
    }
    __syncthreads();

    int nl = t / 16, d = t % 16; int n = n0b + nl;
    float y0 = 0.f, y1[3] = {0.f, 0.f, 0.f};
#pragma unroll
    for (int c = 0; c < 24; c++) {
        y0 += s0[nl][c] * wp[c * 16 + d];
        float w = wp[384 + c * 16 + d];
        y1[0] += s1[nl][c * 3 + 0] * w;
        y1[1] += s1[nl][c * 3 + 1] * w;
        y1[2] += s1[nl][c * 3 + 2] * w;
    }
    {
        float nv = sqrtf(y0 * y0 + 1e-12f);
        float r = nv;
#pragma unroll
        for (int mk = 1; mk < 16; mk <<= 1) r += __shfl_xor_sync(0xffffffffu, r, mk);
        float mu = r * (1.f / 16.f);
        float dv = nv - mu;
        float v = dv * dv;
#pragma unroll
        for (int mk = 1; mk < 16; mk <<= 1) v += __shfl_xor_sync(0xffffffffu, v, mk);
        v *= (1.f / 16.f);
        float ln = dv * rsqrtf(v + 1e-5f) * gamma[d] + beta[d];
        float fac = fmaxf(ln, 0.f) / (nv + 1e-3f);
        g_x0[n * 16 + d] = y0 * fac;
    }
    {
        float nv = sqrtf(y1[0] * y1[0] + y1[1] * y1[1] + y1[2] * y1[2] + 1e-12f);
        float r = nv;
#pragma unroll
        for (int mk = 1; mk < 16; mk <<= 1) r += __shfl_xor_sync(0xffffffffu, r, mk);
        float mu = r * (1.f / 16.f);
        float dv = nv - mu;
        float v = dv * dv;
#pragma unroll
        for (int mk = 1; mk < 16; mk <<= 1) v += __shfl_xor_sync(0xffffffffu, v, mk);
        v *= (1.f / 16.f);
        float ln = dv * rsqrtf(v + 1e-5f) * gamma[16 + d] + beta[16 + d];
        float fac = fmaxf(ln, 0.f) / (nv + 1e-3f);
        g_x1[n * 48 + d * 3 + 0] = y1[0] * fac;
        g_x1[n * 48 + d * 3 + 1] = y1[1] * fac;
        g_x1[n * 48 + d * 3 + 2] = y1[2] * fac;
    }
}

// ---------------- final: init output with self term ----------------
__global__ void k_initout(const float* __restrict__ wself, float* __restrict__ out) {
    int i = blockIdx.x * 256 + threadIdx.x;   // N*32
    if (i >= NN * 32) return;
    int n = i >> 5, j = i & 31;
    float a = 0.f;
    if (j < 8) {
#pragma unroll
        for (int c = 0; c < 16; c++) a += g_x0[n * 16 + c] * wself[c * 8 + j];
    } else {
        int r = j - 8; int o = r / 3, m = r % 3;
#pragma unroll
        for (int c = 0; c < 16; c++) a += g_x1[n * 48 + c * 3 + m] * wself[128 + c * 8 + o];
    }
    out[i] = a;
}

// ---------------- final fc pass (src-CSR): 32 edges x 8 threads(o) ----------------
__global__ void k_edge_fc2(const float* __restrict__ b00, const float* __restrict__ b01,
                           const float* __restrict__ b10, const float* __restrict__ b11,
                           const int* __restrict__ edst, float* __restrict__ out) {
    __shared__ float sP0[128], sP1[128], sP2[384], sP3[1152];
    __shared__ float sH[32][68];
    __shared__ float sB[32][34];
    __shared__ int se[32], sdst[32];
    int n = blockIdx.x;
    int start = g_rs[n], end = g_rs[n + 1];
    if (start == end) return;
    int t = threadIdx.x;
    if (t < 128) { sP0[t] = g_P0[n * 128 + t]; sP1[t] = g_P1[n * 128 + t]; }
    for (int i = t; i < 384; i += 256) sP2[i] = g_P2[n * 384 + i];
    for (int i = t; i < 1152; i += 256) sP3[i] = g_P3[n * 1152 + i];

    int le = t >> 3, o = t & 7;

    for (int c = start; c < end; c += 32) {
        int ne = min(32, end - c);
        __syncthreads();
        if (t < 32) {
            int e = (t < ne) ? g_eperm[c + t] : g_eperm[c];
            se[t] = e;
            sdst[t] = edst[e];
        }
        __syncthreads();
        for (int idx = t; idx < 32 * 64; idx += 256) {
            int lle = idx >> 6, j = idx & 63;
            sH[lle][j] = g_H[se[lle] * 64 + j];
        }
        for (int idx = t; idx < 32 * 34; idx += 256) {
            int lle = idx / 34, j = idx % 34;
            if (lle < ne) {
                int e = se[lle];
                float v;
                if (j == 0)      v = b00[e];
                else if (j < 4)  v = b10[e * 3 + j - 1];
                else if (j < 7)  v = b01[e * 3 + j - 4];
                else             v = b11[e * 27 + j - 7];
                sB[lle][j] = v;
            }
        }
        __syncthreads();
        if (le < ne) {
            float a00 = 0.f, a01 = 0.f;
            float z2[3] = {0.f, 0.f, 0.f};
            float Z[9] = {0.f, 0.f, 0.f, 0.f, 0.f, 0.f, 0.f, 0.f, 0.f};
#pragma unroll
            for (int ht = 0; ht < 4; ht++) {
                const int hb = ht * 4;
                float4 H0 = *(const float4*)&sH[le][0 + hb];
                float4 H1 = *(const float4*)&sH[le][16 + hb];
                float4 H2 = *(const float4*)&sH[le][32 + hb];
                float4 H3 = *(const float4*)&sH[le][48 + hb];
                float h0v[4] = {H0.x, H0.y, H0.z, H0.w};
                float h1v[4] = {H1.x, H1.y, H1.z, H1.w};
                float h2v[4] = {H2.x, H2.y, H2.z, H2.w};
                float h3v[4] = {H3.x, H3.y, H3.z, H3.w};
#pragma unroll
                for (int k = 0; k < 4; k++) {
                    int h = hb + k;
                    a00 += h0v[k] * sP0[h * 8 + o];
                    a01 += h1v[k] * sP1[h * 8 + o];
                    float h2 = h2v[k];
#pragma unroll
                    for (int q = 0; q < 3; q++) z2[q] += h2 * sP2[h * 24 + q * 8 + o];
                    float h3 = h3v[k];
#pragma unroll
                    for (int fq = 0; fq < 9; fq++) Z[fq] += h3 * sP3[h * 72 + fq * 8 + o];
                }
            }
            const float* B = sB[le];
            int dst = sdst[le];
            float m0 = B[0] * a00;
#pragma unroll
            for (int q = 0; q < 3; q++) m0 += B[1 + q] * z2[q];
            atomicAdd(&out[dst * 32 + o], m0);
#pragma unroll
            for (int p = 0; p < 3; p++) {
                float acc = B[4 + p] * a01;
#pragma unroll
                for (int q = 0; q < 3; q++)
#pragma unroll
                    for (int f = 0; f < 3; f++)
                        acc += B[7 + p * 9 + q * 3 + f] * Z[f * 3 + q];
                atomicAdd(&out[dst * 32 + 8 + o * 3 + p], acc);
            }
        }
    }
}

// ---------------- host orchestration ----------------
extern "C" void kernel_launch(void* const* d_in, const int* in_sizes, int n_in,
                              void* d_out, int out_size) {
    const float* x0       = (const float*)d_in[0];
    const float* x1       = (const float*)d_in[1];
    const float* ef       = (const float*)d_in[2];
    const float* b00      = (const float*)d_in[3];
    const float* b01      = (const float*)d_in[4];
    const float* b10      = (const float*)d_in[5];
    const float* b11      = (const float*)d_in[6];
    const float* kv_w1    = (const float*)d_in[7];
    const float* kv_wnf1  = (const float*)d_in[8];
    const float* kv_w11   = (const float*)d_in[9];
    const float* wq       = (const float*)d_in[10];
    const float* wproj    = (const float*)d_in[11];
    const float* gam      = (const float*)d_in[12];
    const float* bet      = (const float*)d_in[13];
    const float* fc_w1    = (const float*)d_in[14];
    const float* fc_wnf1  = (const float*)d_in[15];
    const float* fc_w11   = (const float*)d_in[16];
    const float* fc_wself = (const float*)d_in[17];
    const int*   esrc     = (const int*)d_in[18];
    const int*   edst     = (const int*)d_in[19];
    float* out = (float*)d_out;

    // CSR both directions
    k_csr_zero<<<(NN + 255) / 256, 256>>>();
    k_csr_count<<<EE / 256, 256>>>(esrc, edst);
    k_csr_scan<<<1, 1024>>>();
    k_csr_fill<<<EE / 256, 256>>>(esrc, edst);

    for (int l = 0; l < 2; l++) {
        int use_g = (l != 0);
        k_node_pre3<KV><<<dim3(NN / 128, (224 * KV) / 256), 256>>>(
            x0, x1, use_g,
            kv_wnf1 + l * 3 * MID * KV * CC,
            kv_w11  + l * MID * KV * CC * 3);
        k_H<<<EE / 128, 256>>>(ef, kv_w1 + l * 4 * 16 * 16);
        k_q<<<(NN * 32) / 256, 256>>>(x0, x1, use_g, wq + l * 2 * CC * CKV);
        k_edgeA2<<<NN, 256>>>(b00, b01, b10, b11, edst);
        k_attn<<<(NN * 32) / 256, 256>>>();
        k_nodeD<<<NN / 16, 256>>>(x0, x1, use_g, wproj + l * 768, gam + l * 32, bet + l * 32);
    }
    // final fc pass
    k_node_pre3<CO><<<dim3(NN / 128, (224 * CO) / 256), 256>>>(nullptr, nullptr, 1, fc_wnf1, fc_w11);
    k_H<<<EE / 128, 256>>>(ef, fc_w1);
    k_initout<<<(NN * 32) / 256, 256>>>(fc_wself, out);
    k_edge_fc2<<<NN, 256>>>(b00, b01, b10, b11, edst, out);
}